// round 6
// baseline (speedup 1.0000x reference)
#include <cuda_runtime.h>
#include <cstdint>

#define CIN 3
#define COUT 16
#define HH 32
#define WW 32
#define OH 30
#define OW 30
#define N_IMG 4096
#define GRID 444          /* 148 SMs x 3 blocks */
#define IMG_F4 768        /* 3072 floats per image */

typedef unsigned long long u64;

// ---- f32x2 packed-math helpers (SASS FFMA2 via PTX only) ----
__device__ __forceinline__ u64 pk2(float a, float b) {
    u64 r;
    asm("mov.b64 %0, {%1, %2};" : "=l"(r) : "f"(a), "f"(b));
    return r;
}
__device__ __forceinline__ u64 dup2(float a) {
    u64 r;
    asm("mov.b64 %0, {%1, %1};" : "=l"(r) : "f"(a));
    return r;
}
__device__ __forceinline__ u64 fma2(u64 a, u64 b, u64 c) {
    u64 d;
    asm("fma.rn.f32x2 %0, %1, %2, %3;" : "=l"(d) : "l"(a), "l"(b), "l"(c));
    return d;
}
__device__ __forceinline__ void upk2(u64 v, float& a, float& b) {
    asm("mov.b64 {%0, %1}, %2;" : "=f"(a), "=f"(b) : "l"(v));
}
// activation: relu(v) * min(v+3,6)/6 == max(v,0) * min(v*(1/6)+0.5, 1)
__device__ __forceinline__ float hswish_relu(float v) {
    return fmaxf(v, 0.0f) * fminf(v * (1.0f / 6.0f) + 0.5f, 1.0f);
}

// ---- cp.async helpers ----
__device__ __forceinline__ void cp_async16(uint32_t s, const float4* g) {
    asm volatile("cp.async.cg.shared.global [%0], [%1], 16;" :: "r"(s), "l"(g));
}
__device__ __forceinline__ void cp_commit() {
    asm volatile("cp.async.commit_group;");
}
__device__ __forceinline__ void cp_wait0() {
    asm volatile("cp.async.wait_group 0;" ::: "memory");
}

// Persistent blocks: grid = 444 = one full wave at 3 blocks/SM. Each block
// loops over images (stride 444). Weights packed ONCE per block. Images are
// streamed into a double-buffered smem tile via cp.async.cg, fetched one
// image ahead -> DRAM latency hidden, one __syncthreads per image.
//
// Per image: 128 threads = 4 warps; warp w computes channels 4w..4w+3 as two
// f32x2 accumulator sets (each loaded input value feeds 6 FFMA2). Streaming
// over input rows r: row r feeds output rows r (ky0), r-1 (ky1), r-2 (ky2);
// row r+1 prefetched a full iteration ahead. Fully unrolled.
__global__ void __launch_bounds__(128, 3) conv3x3_hswish_kernel(
    const float* __restrict__ x,
    const float* __restrict__ wgt,
    const float* __restrict__ bias,
    float* __restrict__ out)
{
    // double-buffered image tile (+2 float4 pad: lanes 30/31 over-read)
    __shared__ float4 s_buf[2][IMG_F4 + 2];

    const int tid  = threadIdx.x;
    const int warp = tid >> 5;
    const int lane = tid & 31;
    const int c0   = warp * 4;

    // ---- weights: once per block ----
    u64 wpA[27], wpB[27];
    #pragma unroll
    for (int t = 0; t < 27; t++) {
        wpA[t] = pk2(wgt[(c0 + 0) * 27 + t], wgt[(c0 + 1) * 27 + t]);
        wpB[t] = pk2(wgt[(c0 + 2) * 27 + t], wgt[(c0 + 3) * 27 + t]);
    }
    const u64 bpA = pk2(bias[c0 + 0], bias[c0 + 1]);
    const u64 bpB = pk2(bias[c0 + 2], bias[c0 + 3]);

    const uint32_t sb0 = (uint32_t)__cvta_generic_to_shared(&s_buf[0][0]);
    const uint32_t sb1 = (uint32_t)__cvta_generic_to_shared(&s_buf[1][0]);

    // ---- prologue: fetch first image into buf 0 ----
    int n = blockIdx.x;
    {
        const float4* src = reinterpret_cast<const float4*>(x) + (size_t)n * IMG_F4;
        #pragma unroll
        for (int i = 0; i < 6; i++)
            cp_async16(sb0 + (uint32_t)(tid + i * 128) * 16u, src + tid + i * 128);
        cp_commit();
        cp_wait0();
    }
    __syncthreads();

    int buf = 0;
    #pragma unroll 1
    for (; n < N_IMG; ) {
        const int n_next = n + GRID;

        // issue async fetch of next image into the other buffer
        if (n_next < N_IMG) {
            const float4* src = reinterpret_cast<const float4*>(x) + (size_t)n_next * IMG_F4;
            const uint32_t sdst = buf ? sb0 : sb1;
            #pragma unroll
            for (int i = 0; i < 6; i++)
                cp_async16(sdst + (uint32_t)(tid + i * 128) * 16u, src + tid + i * 128);
        }
        cp_commit();

        // ---- compute image n from s_buf[buf] ----
        const float* base = reinterpret_cast<const float*>(&s_buf[buf][0]) + lane;
        float* out0 = out + ((size_t)n * COUT + c0) * (OH * OW) + lane;

        float nb0[9], nb1[9];
        u64 accA[3], accB[3];

        #pragma unroll
        for (int ci = 0; ci < CIN; ci++)
            #pragma unroll
            for (int kx = 0; kx < 3; kx++)
                nb0[ci * 3 + kx] = base[ci * 1024 + kx];   // input row 0

        #pragma unroll
        for (int r = 0; r < 32; r++) {
            if (r < 31) {   // prefetch input row r+1
                #pragma unroll
                for (int ci = 0; ci < CIN; ci++)
                    #pragma unroll
                    for (int kx = 0; kx < 3; kx++) {
                        float v = base[ci * 1024 + (r + 1) * 32 + kx];
                        if (r & 1) nb0[ci * 3 + kx] = v; else nb1[ci * 3 + kx] = v;
                    }
            }

            if (r <= 29) { accA[r % 3] = bpA; accB[r % 3] = bpB; }

            #pragma unroll
            for (int t = 0; t < 9; t++) {
                const int ci = t / 3, kx = t % 3;
                const u64 dv = dup2((r & 1) ? nb1[t] : nb0[t]);
                if (r >= 2) {
                    accA[(r - 2) % 3] = fma2(dv, wpA[ci * 9 + 6 + kx], accA[(r - 2) % 3]);
                    accB[(r - 2) % 3] = fma2(dv, wpB[ci * 9 + 6 + kx], accB[(r - 2) % 3]);
                }
                if (r >= 1 && r <= 30) {
                    accA[(r - 1) % 3] = fma2(dv, wpA[ci * 9 + 3 + kx], accA[(r - 1) % 3]);
                    accB[(r - 1) % 3] = fma2(dv, wpB[ci * 9 + 3 + kx], accB[(r - 1) % 3]);
                }
                if (r <= 29) {
                    accA[r % 3] = fma2(dv, wpA[ci * 9 + 0 + kx], accA[r % 3]);
                    accB[r % 3] = fma2(dv, wpB[ci * 9 + 0 + kx], accB[r % 3]);
                }
            }

            if (r >= 2 && lane < OW) {   // output row r-2 complete
                const int yoff = (r - 2) * OW;
                float v0, v1, v2, v3;
                upk2(accA[(r - 2) % 3], v0, v1);
                upk2(accB[(r - 2) % 3], v2, v3);
                out0[0 * OH * OW + yoff] = hswish_relu(v0);
                out0[1 * OH * OW + yoff] = hswish_relu(v1);
                out0[2 * OH * OW + yoff] = hswish_relu(v2);
                out0[3 * OH * OW + yoff] = hswish_relu(v3);
            }
        }

        // next image's data must be resident; all warps done with old buffer
        cp_wait0();
        __syncthreads();
        buf ^= 1;
        n = n_next;
    }
}

extern "C" void kernel_launch(void* const* d_in, const int* in_sizes, int n_in,
                              void* d_out, int out_size) {
    const float* x = (const float*)d_in[0];
    const float* w = (const float*)d_in[1];
    const float* b = (const float*)d_in[2];
    float* out = (float*)d_out;

    conv3x3_hswish_kernel<<<GRID, 128>>>(x, w, b, out);
}